// round 2
// baseline (speedup 1.0000x reference)
#include <cuda_runtime.h>
#include <math.h>

// Problem constants
#define B_   32
#define IU_  16
#define IC_  2048
#define NU_  16
#define US_  64
#define ICHUNKS 32
#define CHUNK (IC_/ICHUNKS)   // 64

// Scratch (device globals: allocation-free)
__device__ float g_xT[IC_*IU_*B_];                 // [i][u][b]  = 4 MB
__device__ float g_part[(size_t)ICHUNKS*B_*NU_*US_]; // [chunk][b][j][k] = 4 MB

// ---------------------------------------------------------------------------
// Kernel 1: transpose x[b][u][i] -> xT[i][u][b], coalesced both sides.
// grid (IC/32, IU), block (32, 8)
// ---------------------------------------------------------------------------
__global__ void transpose_kernel(const float* __restrict__ x) {
    __shared__ float tile[32][33];
    int u  = blockIdx.y;
    int i0 = blockIdx.x * 32;
    int tx = threadIdx.x;   // i within tile on load, b on store
    int ty = threadIdx.y;

    #pragma unroll
    for (int p = 0; p < 4; ++p) {
        int b = ty + p * 8;                 // 0..31
        tile[b][tx] = x[((size_t)b * IU_ + u) * IC_ + i0 + tx];
    }
    __syncthreads();
    #pragma unroll
    for (int p = 0; p < 4; ++p) {
        int il = ty + p * 8;                // local i
        g_xT[(size_t)(i0 + il) * (IU_ * B_) + u * B_ + tx] = tile[tx][il];
    }
}

// ---------------------------------------------------------------------------
// Kernel 2: GEMM partials.
//   part[chunk][b][j][k] = sum_{i in chunk, u} W[i][j][k][u] * xT[i][u][b]
// grid (ICHUNKS, NU), block 256 (8 warps). Warp w owns k = w*8..w*8+7, lane = b.
// W[i][j][*][*] is 1024 contiguous floats -> double-buffered 4 KB smem tile.
// ---------------------------------------------------------------------------
__global__ void gemm_kernel(const float* __restrict__ W) {
    __shared__ float Wsm[2][1024];
    const int j     = blockIdx.y;
    const int chunk = blockIdx.x;
    const int i0    = chunk * CHUNK;
    const int tid   = threadIdx.x;
    const int warp  = tid >> 5;
    const int lane  = tid & 31;

    float acc[8];
    #pragma unroll
    for (int kk = 0; kk < 8; ++kk) acc[kk] = 0.f;

    // W base for this block, viewed as float4; consecutive i stride = 16384/4
    const float4* __restrict__ w0 =
        (const float4*)(W + (size_t)i0 * (NU_ * US_ * IU_) + (size_t)j * (US_ * IU_));

    // preload i0
    ((float4*)Wsm[0])[tid] = w0[tid];
    __syncthreads();

    for (int ii = 0; ii < CHUNK; ++ii) {
        const int cur = ii & 1;

        // prefetch next W tile (issue LDG early)
        float4 wn;
        const bool has_next = (ii + 1 < CHUNK);
        if (has_next) wn = w0[(size_t)(ii + 1) * 4096 + tid];

        // x registers for this i (coalesced, L2-resident)
        float xr[16];
        const float* __restrict__ xp = g_xT + (size_t)(i0 + ii) * (IU_ * B_) + lane;
        #pragma unroll
        for (int u = 0; u < 16; ++u) xr[u] = xp[u * B_];

        if (has_next) ((float4*)Wsm[cur ^ 1])[tid] = wn;

        const float* __restrict__ wbase = Wsm[cur] + warp * 8 * 16;
        #pragma unroll
        for (int kk = 0; kk < 8; ++kk) {
            const float4* __restrict__ wr = (const float4*)(wbase + kk * 16);
            float4 a = wr[0], b4 = wr[1], c = wr[2], d = wr[3];
            float s = acc[kk];
            s += a.x  * xr[0];  s += a.y  * xr[1];  s += a.z  * xr[2];  s += a.w  * xr[3];
            s += b4.x * xr[4];  s += b4.y * xr[5];  s += b4.z * xr[6];  s += b4.w * xr[7];
            s += c.x  * xr[8];  s += c.y  * xr[9];  s += c.z  * xr[10]; s += c.w  * xr[11];
            s += d.x  * xr[12]; s += d.y  * xr[13]; s += d.z  * xr[14]; s += d.w  * xr[15];
            acc[kk] = s;
        }
        __syncthreads();
    }

    // store partials: part[chunk][b=lane][j][k=warp*8+kk]
    float* __restrict__ pout =
        g_part + ((size_t)(chunk * B_ + lane) * NU_ + j) * US_ + warp * 8;
    #pragma unroll
    for (int kk = 0; kk < 8; ++kk) pout[kk] = acc[kk];
}

// ---------------------------------------------------------------------------
// Kernel 3: reduce partials over chunks, squash, write out.
//   s[b,j,k] = sum_c part[c][b][j][k]
//   msq[b,k] = sum_j s^2 ;  out = s * mag/(1+msq)
// grid B_, block US_
// ---------------------------------------------------------------------------
__global__ void squash_kernel(float* __restrict__ out) {
    const int b = blockIdx.x;
    const int k = threadIdx.x;

    float sv[NU_];
    float msq = 0.f;
    #pragma unroll
    for (int j = 0; j < NU_; ++j) {
        float v = 0.f;
        #pragma unroll
        for (int c = 0; c < ICHUNKS; ++c)
            v += g_part[((size_t)(c * B_ + b) * NU_ + j) * US_ + k];
        sv[j] = v;
        msq += v * v;
    }
    const float mag = sqrtf(msq);
    const float f   = mag / (1.0f + msq);
    #pragma unroll
    for (int j = 0; j < NU_; ++j)
        out[((size_t)b * NU_ + j) * US_ + k] = sv[j] * f;
}

// ---------------------------------------------------------------------------
extern "C" void kernel_launch(void* const* d_in, const int* in_sizes, int n_in,
                              void* d_out, int out_size) {
    const float* x = (const float*)d_in[0];
    const float* W = (const float*)d_in[1];
    // robust to input ordering: x has 1,048,576 elems, W has 33,554,432
    if (in_sizes[0] != B_ * IU_ * IC_) { const float* t = x; x = W; W = t; }

    transpose_kernel<<<dim3(IC_ / 32, IU_), dim3(32, 8)>>>(x);
    gemm_kernel<<<dim3(ICHUNKS, NU_), 256>>>(W);
    squash_kernel<<<B_, US_>>>((float*)d_out);
}

// round 5
// speedup vs baseline: 2.3437x; 2.3437x over previous
#include <cuda_runtime.h>
#include <math.h>
#include <stdint.h>

// Problem constants
#define B_   32
#define IU_  16
#define IC_  2048
#define NU_  16
#define US_  64
#define ICHUNKS 32
#define CHUNK (IC_/ICHUNKS)   // 64

// Scratch (device globals: allocation-free)
// Apk[i][slot][lane][r]  slot = t*2+mt, 4 floats per lane  -> 2048*4*32*4 floats = 4 MB
__device__ float g_Apk[(size_t)IC_ * 4 * 32 * 4];
// part[chunk][b][j][k] = 4 MB
__device__ float g_part[(size_t)ICHUNKS * B_ * NU_ * US_];

// ---------------------------------------------------------------------------
// Kernel 1: repack x[b][u][i] into mma A-fragment order with the K-permutation
//   logical col c (0..7), step t (0..1)  ->  u = 4*(c%4) + 2t + (c>=4)
// Fragment slots per (i, t, mt): lane l r0: (b=l/4+16mt,      u=4(l%4)+2t)
//                                       r1: (b=l/4+16mt+8,    same u)
//                                       r2: (b=l/4+16mt,      u+1)
//                                       r3: (b=l/4+16mt+8,    u+1)
// grid 128, block 256; each block handles 16 consecutive i.
// ---------------------------------------------------------------------------
__global__ void prep_kernel(const float* __restrict__ x) {
    __shared__ float xs[B_][IU_][16];   // [b][u][i_local] = 32 KB
    const int i0 = blockIdx.x * 16;

    // load: 512 (b,u) rows x 16 floats, via float4 (2048 float4 total)
    for (int q = threadIdx.x; q < 2048; q += 256) {
        int bu = q >> 2;            // 0..511
        int f  = q & 3;             // float4 index within the 16-float row
        int b  = bu >> 4, u = bu & 15;
        float4 v = *(const float4*)(x + ((size_t)b * IU_ + u) * IC_ + i0 + f * 4);
        xs[b][u][f*4+0] = v.x; xs[b][u][f*4+1] = v.y;
        xs[b][u][f*4+2] = v.z; xs[b][u][f*4+3] = v.w;
    }
    __syncthreads();

    // write: 16 i x 4 slots x 32 lanes float4, contiguous & coalesced
    for (int q = threadIdx.x; q < 2048; q += 256) {
        int lane = q & 31;
        int slot = (q >> 5) & 3;
        int il   = q >> 7;
        int t  = slot >> 1, mt = slot & 1;
        int b0 = (lane >> 2) + 16 * mt;
        int u0 = 4 * (lane & 3) + 2 * t;
        float4 v;
        v.x = xs[b0    ][u0    ][il];
        v.y = xs[b0 + 8][u0    ][il];
        v.z = xs[b0    ][u0 + 1][il];
        v.w = xs[b0 + 8][u0 + 1][il];
        *(float4*)(g_Apk + (((size_t)(i0 + il) * 4 + slot) * 32 + lane) * 4) = v;
    }
}

// ---------------------------------------------------------------------------
__device__ __forceinline__ uint32_t f2tf(float f) {
    uint32_t r;
    asm("cvt.rna.tf32.f32 %0, %1;" : "=r"(r) : "f"(f));
    return r;
}

__device__ __forceinline__ void mma_tf32(float c[4], const uint32_t a[4],
                                         uint32_t b0, uint32_t b1) {
    asm volatile(
        "mma.sync.aligned.m16n8k8.row.col.f32.tf32.tf32.f32 "
        "{%0,%1,%2,%3}, {%4,%5,%6,%7}, {%8,%9}, {%0,%1,%2,%3};"
        : "+f"(c[0]), "+f"(c[1]), "+f"(c[2]), "+f"(c[3])
        : "r"(a[0]), "r"(a[1]), "r"(a[2]), "r"(a[3]), "r"(b0), "r"(b1));
}

// ---------------------------------------------------------------------------
// Kernel 2: tf32 tensor-core GEMM partials.
// grid (ICHUNKS, NU), block 256 (8 warps); warp w -> capsule-k block kc0 = 8w.
// Per i: one LDG.128/lane of W (streamed, used once), four LDG.128/lane of Apk
// (L1/L2 resident), 4 mma.
// ---------------------------------------------------------------------------
__global__ void __launch_bounds__(256, 4) gemm_kernel(const float* __restrict__ W) {
    const int j     = blockIdx.y;
    const int chunk = blockIdx.x;
    const int warp  = threadIdx.x >> 5;
    const int lane  = threadIdx.x & 31;
    const int kc0   = warp * 8;

    float c0[4] = {0.f, 0.f, 0.f, 0.f};   // rows 0-15  (mt=0)
    float c1[4] = {0.f, 0.f, 0.f, 0.f};   // rows 16-31 (mt=1)

    // W float4 base for (i = chunk*64, j, kc0): element off = ((i*16+j)*64+kc0)*16
    const float4* __restrict__ bp =
        (const float4*)(W + (((size_t)chunk * CHUNK * NU_ + j) * US_ + kc0) * IU_) + lane;
    // Apk float4 base for i = chunk*64
    const float4* __restrict__ ap =
        (const float4*)(g_Apk) + (size_t)chunk * CHUNK * 128 + lane;

    #pragma unroll 4
    for (int ii = 0; ii < CHUNK; ++ii) {
        float4 bv = bp[(size_t)ii * 4096];          // i-stride = 16384 floats
        float4 a0 = ap[ii * 128 +  0];              // slot0: t0,mt0
        float4 a1 = ap[ii * 128 + 32];              // slot1: t0,mt1
        float4 a2 = ap[ii * 128 + 64];              // slot2: t1,mt0
        float4 a3 = ap[ii * 128 + 96];              // slot3: t1,mt1

        uint32_t bt[4] = { f2tf(bv.x), f2tf(bv.y), f2tf(bv.z), f2tf(bv.w) };
        uint32_t f0[4] = { f2tf(a0.x), f2tf(a0.y), f2tf(a0.z), f2tf(a0.w) };
        uint32_t f1[4] = { f2tf(a1.x), f2tf(a1.y), f2tf(a1.z), f2tf(a1.w) };
        uint32_t f2[4] = { f2tf(a2.x), f2tf(a2.y), f2tf(a2.z), f2tf(a2.w) };
        uint32_t f3[4] = { f2tf(a3.x), f2tf(a3.y), f2tf(a3.z), f2tf(a3.w) };

        mma_tf32(c0, f0, bt[0], bt[1]);   // t=0, rows 0-15
        mma_tf32(c1, f1, bt[0], bt[1]);   // t=0, rows 16-31
        mma_tf32(c0, f2, bt[2], bt[3]);   // t=1, rows 0-15
        mma_tf32(c1, f3, bt[2], bt[3]);   // t=1, rows 16-31
    }

    // C frag: lane -> rows l/4 (+8), cols kc0 + 2*(l%4) (+1)
    const int brow = lane >> 2;
    const int kc   = kc0 + 2 * (lane & 3);
    const size_t base = ((size_t)chunk * B_ * NU_ + j) * US_ + kc;   // b=0 slot
    const size_t bstr = (size_t)NU_ * US_;                            // +1 batch

    *(float2*)(g_part + base + (brow     ) * bstr) = make_float2(c0[0], c0[1]);
    *(float2*)(g_part + base + (brow +  8) * bstr) = make_float2(c0[2], c0[3]);
    *(float2*)(g_part + base + (brow + 16) * bstr) = make_float2(c1[0], c1[1]);
    *(float2*)(g_part + base + (brow + 24) * bstr) = make_float2(c1[2], c1[3]);
}

// ---------------------------------------------------------------------------
// Kernel 3: reduce partials over chunks, squash, write out.
// grid B_, block US_
// ---------------------------------------------------------------------------
__global__ void squash_kernel(float* __restrict__ out) {
    const int b = blockIdx.x;
    const int k = threadIdx.x;

    float sv[NU_];
    float msq = 0.f;
    #pragma unroll
    for (int j = 0; j < NU_; ++j) {
        float v = 0.f;
        #pragma unroll
        for (int c = 0; c < ICHUNKS; ++c)
            v += g_part[((size_t)(c * B_ + b) * NU_ + j) * US_ + k];
        sv[j] = v;
        msq += v * v;
    }
    const float mag = sqrtf(msq);
    const float f   = mag / (1.0f + msq);
    #pragma unroll
    for (int j = 0; j < NU_; ++j)
        out[((size_t)b * NU_ + j) * US_ + k] = sv[j] * f;
}

// ---------------------------------------------------------------------------
extern "C" void kernel_launch(void* const* d_in, const int* in_sizes, int n_in,
                              void* d_out, int out_size) {
    const float* x = (const float*)d_in[0];
    const float* W = (const float*)d_in[1];
    if (in_sizes[0] != B_ * IU_ * IC_) { const float* t = x; x = W; W = t; }

    prep_kernel<<<IC_ / 16, 256>>>(x);
    gemm_kernel<<<dim3(ICHUNKS, NU_), 256>>>(W);
    squash_kernel<<<B_, US_>>>((float*)d_out);
}

// round 8
// speedup vs baseline: 3.5036x; 1.4949x over previous
#include <cuda_runtime.h>
#include <math.h>
#include <stdint.h>

// Problem constants
#define B_   32
#define IU_  16
#define IC_  2048
#define NU_  16
#define US_  64
#define ICH  64            // chunks over i
#define CH   (IC_/ICH)     // 32 i per chunk

// Scratch (device globals: allocation-free)
__device__ float g_Apk[(size_t)IC_ * 4 * 32 * 4];              // 4 MB, mma A-frag order
__device__ float g_part[(size_t)ICH * B_ * NU_ * US_];         // 8 MB [chunk][b][j][k]
__device__ float g_part2[(size_t)4 * B_ * NU_ * US_];          // 512 KB [c4][b][j][k]

// ---------------------------------------------------------------------------
// Kernel 1: repack x[b][u][i] into mma A-fragment order (K-permutation baked in)
//   slot = t*2+mt; lane l: r0:(b=l/4+16mt, u=4(l%4)+2t) r1:(b+8,u) r2:(b,u+1) r3:(b+8,u+1)
// grid 256, block 256; 8 i per block.
// ---------------------------------------------------------------------------
__global__ void prep_kernel(const float* __restrict__ x) {
    __shared__ float xs[B_][IU_][9];          // [b][u][il], il<8, pad to 9
    const int i0 = blockIdx.x * 8;

    // load: 512 (b,u) rows x 8 floats (2 float4 each) = 1024 float4
    for (int q = threadIdx.x; q < 1024; q += 256) {
        int bu = q >> 1, f = q & 1;
        int b = bu >> 4, u = bu & 15;
        float4 v = *(const float4*)(x + ((size_t)b * IU_ + u) * IC_ + i0 + f * 4);
        xs[b][u][f*4+0] = v.x; xs[b][u][f*4+1] = v.y;
        xs[b][u][f*4+2] = v.z; xs[b][u][f*4+3] = v.w;
    }
    __syncthreads();

    // store: 8 i x 4 slots x 32 lanes float4, contiguous & coalesced
    for (int q = threadIdx.x; q < 1024; q += 256) {
        int lane = q & 31;
        int slot = (q >> 5) & 3;
        int il   = q >> 7;                    // 0..7
        int t  = slot >> 1, mt = slot & 1;
        int b0 = (lane >> 2) + 16 * mt;
        int u0 = 4 * (lane & 3) + 2 * t;
        float4 v;
        v.x = xs[b0    ][u0    ][il];
        v.y = xs[b0 + 8][u0    ][il];
        v.z = xs[b0    ][u0 + 1][il];
        v.w = xs[b0 + 8][u0 + 1][il];
        *(float4*)(g_Apk + (((size_t)(i0 + il) * 4 + slot) * 32 + lane) * 4) = v;
    }
}

// ---------------------------------------------------------------------------
__device__ __forceinline__ uint32_t f2tf(float f) {
    uint32_t r;
    asm("cvt.rna.tf32.f32 %0, %1;" : "=r"(r) : "f"(f));
    return r;
}

__device__ __forceinline__ void mma_tf32(float c[4], const uint32_t a[4],
                                         uint32_t b0, uint32_t b1) {
    asm volatile(
        "mma.sync.aligned.m16n8k8.row.col.f32.tf32.tf32.f32 "
        "{%0,%1,%2,%3}, {%4,%5,%6,%7}, {%8,%9}, {%0,%1,%2,%3};"
        : "+f"(c[0]), "+f"(c[1]), "+f"(c[2]), "+f"(c[3])
        : "r"(a[0]), "r"(a[1]), "r"(a[2]), "r"(a[3]), "r"(b0), "r"(b1));
}

// ---------------------------------------------------------------------------
// Kernel 2: tf32 GEMM partials. grid (ICH=64, 8 j-pairs), block 256 (8 warps).
// Warp w: kc block = 8w, handles j0 and j0+1 -> one A-fragment load amortized
// over two W streams (2x LDG.128 W : 4x LDG.128 A per i).
// ---------------------------------------------------------------------------
__global__ void __launch_bounds__(256, 2) gemm_kernel(const float* __restrict__ W) {
    const int j0    = blockIdx.y * 2;
    const int chunk = blockIdx.x;
    const int i0    = chunk * CH;
    const int warp  = threadIdx.x >> 5;
    const int lane  = threadIdx.x & 31;
    const int kc0   = warp * 8;

    float cA0[4] = {0,0,0,0}, cA1[4] = {0,0,0,0};   // j0   (mt=0 / mt=1)
    float cB0[4] = {0,0,0,0}, cB1[4] = {0,0,0,0};   // j0+1

    // W float4 base for (i0, j0, kc0): elem off = ((i0*16 + j0)*64 + kc0)*16
    const float4* __restrict__ bp =
        (const float4*)(W + (((size_t)i0 * NU_ + j0) * US_ + kc0) * IU_) + lane;
    const float4* __restrict__ ap =
        (const float4*)(g_Apk) + (size_t)i0 * 128 + lane;

    #pragma unroll 4
    for (int ii = 0; ii < CH; ++ii) {
        float4 bA = bp[(size_t)ii * 4096];           // i stride = 16384 floats
        float4 bB = bp[(size_t)ii * 4096 + 256];     // +1 j    = 1024 floats
        float4 a0 = ap[ii * 128 +  0];
        float4 a1 = ap[ii * 128 + 32];
        float4 a2 = ap[ii * 128 + 64];
        float4 a3 = ap[ii * 128 + 96];

        uint32_t btA[4] = { f2tf(bA.x), f2tf(bA.y), f2tf(bA.z), f2tf(bA.w) };
        uint32_t btB[4] = { f2tf(bB.x), f2tf(bB.y), f2tf(bB.z), f2tf(bB.w) };
        uint32_t f0[4]  = { f2tf(a0.x), f2tf(a0.y), f2tf(a0.z), f2tf(a0.w) };
        uint32_t f1[4]  = { f2tf(a1.x), f2tf(a1.y), f2tf(a1.z), f2tf(a1.w) };
        uint32_t f2v[4] = { f2tf(a2.x), f2tf(a2.y), f2tf(a2.z), f2tf(a2.w) };
        uint32_t f3[4]  = { f2tf(a3.x), f2tf(a3.y), f2tf(a3.z), f2tf(a3.w) };

        mma_tf32(cA0, f0,  btA[0], btA[1]);   // j0,   t=0
        mma_tf32(cA1, f1,  btA[0], btA[1]);
        mma_tf32(cA0, f2v, btA[2], btA[3]);   // j0,   t=1
        mma_tf32(cA1, f3,  btA[2], btA[3]);
        mma_tf32(cB0, f0,  btB[0], btB[1]);   // j0+1, t=0
        mma_tf32(cB1, f1,  btB[0], btB[1]);
        mma_tf32(cB0, f2v, btB[2], btB[3]);   // j0+1, t=1
        mma_tf32(cB1, f3,  btB[2], btB[3]);
    }

    // C frag: lane -> rows l/4 (+8 / +16 / +24), cols kc0 + 2*(l%4) (+1)
    const int brow = lane >> 2;
    const int kc   = kc0 + 2 * (lane & 3);
    const size_t bstr = (size_t)NU_ * US_;                    // +1 batch
    const size_t baseA = ((size_t)chunk * B_ * NU_ + j0) * US_ + kc;
    const size_t baseB = baseA + US_;                          // j0+1

    *(float2*)(g_part + baseA + (brow     ) * bstr) = make_float2(cA0[0], cA0[1]);
    *(float2*)(g_part + baseA + (brow +  8) * bstr) = make_float2(cA0[2], cA0[3]);
    *(float2*)(g_part + baseA + (brow + 16) * bstr) = make_float2(cA1[0], cA1[1]);
    *(float2*)(g_part + baseA + (brow + 24) * bstr) = make_float2(cA1[2], cA1[3]);
    *(float2*)(g_part + baseB + (brow     ) * bstr) = make_float2(cB0[0], cB0[1]);
    *(float2*)(g_part + baseB + (brow +  8) * bstr) = make_float2(cB0[2], cB0[3]);
    *(float2*)(g_part + baseB + (brow + 16) * bstr) = make_float2(cB1[0], cB1[1]);
    *(float2*)(g_part + baseB + (brow + 24) * bstr) = make_float2(cB1[2], cB1[3]);
}

// ---------------------------------------------------------------------------
// Kernel 3a: reduce 64 chunk-partials -> 4. grid 512, block 256, coalesced.
// ---------------------------------------------------------------------------
__global__ void reduce_kernel() {
    const int idx = blockIdx.x * 256 + threadIdx.x;   // 0..131071
    const int c4  = idx >> 15;                        // 0..3
    const int rem = idx & 32767;                      // (b,j,k)
    float s = 0.f;
    #pragma unroll
    for (int m = 0; m < 16; ++m)
        s += g_part[(size_t)(c4 * 16 + m) * 32768 + rem];
    g_part2[idx] = s;
}

// ---------------------------------------------------------------------------
// Kernel 3b: final sum over 4 partials + squash. grid B_, block (US_, NU_).
// ---------------------------------------------------------------------------
__global__ void squash_kernel(float* __restrict__ out) {
    __shared__ float vbuf[NU_][US_ + 1];
    __shared__ float fbuf[US_];
    const int b = blockIdx.x;
    const int k = threadIdx.x;
    const int j = threadIdx.y;

    float v = 0.f;
    #pragma unroll
    for (int c = 0; c < 4; ++c)
        v += g_part2[(size_t)c * 32768 + ((size_t)b * NU_ + j) * US_ + k];
    vbuf[j][k] = v;
    __syncthreads();

    if (j == 0) {
        float msq = 0.f;
        #pragma unroll
        for (int jj = 0; jj < NU_; ++jj) {
            float t = vbuf[jj][k];
            msq += t * t;
        }
        fbuf[k] = sqrtf(msq) / (1.0f + msq);
    }
    __syncthreads();

    out[((size_t)b * NU_ + j) * US_ + k] = v * fbuf[k];
}

// ---------------------------------------------------------------------------
extern "C" void kernel_launch(void* const* d_in, const int* in_sizes, int n_in,
                              void* d_out, int out_size) {
    const float* x = (const float*)d_in[0];
    const float* W = (const float*)d_in[1];
    if (in_sizes[0] != B_ * IU_ * IC_) { const float* t = x; x = W; W = t; }

    prep_kernel<<<IC_ / 8, 256>>>(x);
    gemm_kernel<<<dim3(ICH, NU_ / 2), 256>>>(W);
    reduce_kernel<<<512, 256>>>();
    squash_kernel<<<B_, dim3(US_, NU_)>>>((float*)d_out);
}

// round 9
// speedup vs baseline: 3.7978x; 1.0840x over previous
#include <cuda_runtime.h>
#include <math.h>
#include <stdint.h>

// Problem constants
#define B_   32
#define IU_  16
#define IC_  2048
#define NU_  16
#define US_  64
#define ICH  64            // chunks over i
#define CH   (IC_/ICH)     // 32 i per chunk

// Scratch (device globals: allocation-free)
__device__ float g_Apk[(size_t)IC_ * 4 * 32 * 4];              // 4 MB, mma A-frag order
__device__ float g_part[(size_t)ICH * B_ * NU_ * US_];         // 8 MB [chunk][b][j][k]

// ---------------------------------------------------------------------------
// Kernel 1: repack x[b][u][i] into mma A-fragment order (K-permutation baked in)
// grid 256, block 256; 8 i per block.
// ---------------------------------------------------------------------------
__global__ void prep_kernel(const float* __restrict__ x) {
    __shared__ float xs[B_][IU_][9];          // [b][u][il], il<8, pad to 9
    const int i0 = blockIdx.x * 8;

    for (int q = threadIdx.x; q < 1024; q += 256) {
        int bu = q >> 1, f = q & 1;
        int b = bu >> 4, u = bu & 15;
        float4 v = *(const float4*)(x + ((size_t)b * IU_ + u) * IC_ + i0 + f * 4);
        xs[b][u][f*4+0] = v.x; xs[b][u][f*4+1] = v.y;
        xs[b][u][f*4+2] = v.z; xs[b][u][f*4+3] = v.w;
    }
    __syncthreads();

    for (int q = threadIdx.x; q < 1024; q += 256) {
        int lane = q & 31;
        int slot = (q >> 5) & 3;
        int il   = q >> 7;                    // 0..7
        int t  = slot >> 1, mt = slot & 1;
        int b0 = (lane >> 2) + 16 * mt;
        int u0 = 4 * (lane & 3) + 2 * t;
        float4 v;
        v.x = xs[b0    ][u0    ][il];
        v.y = xs[b0 + 8][u0    ][il];
        v.z = xs[b0    ][u0 + 1][il];
        v.w = xs[b0 + 8][u0 + 1][il];
        *(float4*)(g_Apk + (((size_t)(i0 + il) * 4 + slot) * 32 + lane) * 4) = v;
    }
}

// ---------------------------------------------------------------------------
__device__ __forceinline__ uint32_t f2tf(float f) {
    uint32_t r;
    asm("cvt.rna.tf32.f32 %0, %1;" : "=r"(r) : "f"(f));
    return r;
}

__device__ __forceinline__ void mma_tf32(float c[4], const uint32_t a[4],
                                         uint32_t b0, uint32_t b1) {
    asm volatile(
        "mma.sync.aligned.m16n8k8.row.col.f32.tf32.tf32.f32 "
        "{%0,%1,%2,%3}, {%4,%5,%6,%7}, {%8,%9}, {%0,%1,%2,%3};"
        : "+f"(c[0]), "+f"(c[1]), "+f"(c[2]), "+f"(c[3])
        : "r"(a[0]), "r"(a[1]), "r"(a[2]), "r"(a[3]), "r"(b0), "r"(b1));
}

__device__ __forceinline__ float4 ldcs4(const float4* p) {
    float4 v;
    asm volatile("ld.global.cs.v4.f32 {%0,%1,%2,%3}, [%4];"
                 : "=f"(v.x), "=f"(v.y), "=f"(v.z), "=f"(v.w) : "l"(p));
    return v;
}

// ---------------------------------------------------------------------------
// Kernel 2: tf32 GEMM partials. grid (ICH=64, 8 j-pairs), block 256 (8 warps).
// Warp w: kc block = 8w, handles j0 and j0+1. W is streamed with evict-first
// (__ldcs) so the 4 MB A stays L2-resident. Explicit 1-deep register pipeline
// keeps 12 LDG.128 in flight per warp.
// ---------------------------------------------------------------------------
__global__ void __launch_bounds__(256, 2) gemm_kernel(const float* __restrict__ W) {
    const int j0    = blockIdx.y * 2;
    const int chunk = blockIdx.x;
    const int i0    = chunk * CH;
    const int warp  = threadIdx.x >> 5;
    const int lane  = threadIdx.x & 31;
    const int kc0   = warp * 8;

    float cA0[4] = {0,0,0,0}, cA1[4] = {0,0,0,0};   // j0   (mt=0 / mt=1)
    float cB0[4] = {0,0,0,0}, cB1[4] = {0,0,0,0};   // j0+1

    const float4* __restrict__ bp =
        (const float4*)(W + (((size_t)i0 * NU_ + j0) * US_ + kc0) * IU_) + lane;
    const float4* __restrict__ ap =
        (const float4*)(g_Apk) + (size_t)i0 * 128 + lane;

    // pipeline preload (ii = 0)
    float4 nbA = ldcs4(bp);
    float4 nbB = ldcs4(bp + 256);
    float4 na0 = ap[0], na1 = ap[32], na2 = ap[64], na3 = ap[96];

    #pragma unroll 4
    for (int ii = 0; ii < CH; ++ii) {
        float4 bA = nbA, bB = nbB;
        float4 a0 = na0, a1 = na1, a2 = na2, a3 = na3;

        if (ii + 1 < CH) {
            const size_t wo = (size_t)(ii + 1) * 4096;
            const int    ao = (ii + 1) * 128;
            nbA = ldcs4(bp + wo);
            nbB = ldcs4(bp + wo + 256);
            na0 = ap[ao +  0];
            na1 = ap[ao + 32];
            na2 = ap[ao + 64];
            na3 = ap[ao + 96];
        }

        uint32_t btA[4] = { f2tf(bA.x), f2tf(bA.y), f2tf(bA.z), f2tf(bA.w) };
        uint32_t btB[4] = { f2tf(bB.x), f2tf(bB.y), f2tf(bB.z), f2tf(bB.w) };
        uint32_t f0[4]  = { f2tf(a0.x), f2tf(a0.y), f2tf(a0.z), f2tf(a0.w) };
        uint32_t f1[4]  = { f2tf(a1.x), f2tf(a1.y), f2tf(a1.z), f2tf(a1.w) };
        uint32_t f2v[4] = { f2tf(a2.x), f2tf(a2.y), f2tf(a2.z), f2tf(a2.w) };
        uint32_t f3[4]  = { f2tf(a3.x), f2tf(a3.y), f2tf(a3.z), f2tf(a3.w) };

        mma_tf32(cA0, f0,  btA[0], btA[1]);
        mma_tf32(cA1, f1,  btA[0], btA[1]);
        mma_tf32(cA0, f2v, btA[2], btA[3]);
        mma_tf32(cA1, f3,  btA[2], btA[3]);
        mma_tf32(cB0, f0,  btB[0], btB[1]);
        mma_tf32(cB1, f1,  btB[0], btB[1]);
        mma_tf32(cB0, f2v, btB[2], btB[3]);
        mma_tf32(cB1, f3,  btB[2], btB[3]);
    }

    const int brow = lane >> 2;
    const int kc   = kc0 + 2 * (lane & 3);
    const size_t bstr = (size_t)NU_ * US_;
    const size_t baseA = ((size_t)chunk * B_ * NU_ + j0) * US_ + kc;
    const size_t baseB = baseA + US_;

    *(float2*)(g_part + baseA + (brow     ) * bstr) = make_float2(cA0[0], cA0[1]);
    *(float2*)(g_part + baseA + (brow +  8) * bstr) = make_float2(cA0[2], cA0[3]);
    *(float2*)(g_part + baseA + (brow + 16) * bstr) = make_float2(cA1[0], cA1[1]);
    *(float2*)(g_part + baseA + (brow + 24) * bstr) = make_float2(cA1[2], cA1[3]);
    *(float2*)(g_part + baseB + (brow     ) * bstr) = make_float2(cB0[0], cB0[1]);
    *(float2*)(g_part + baseB + (brow +  8) * bstr) = make_float2(cB0[2], cB0[3]);
    *(float2*)(g_part + baseB + (brow + 16) * bstr) = make_float2(cB1[0], cB1[1]);
    *(float2*)(g_part + baseB + (brow + 24) * bstr) = make_float2(cB1[2], cB1[3]);
}

// ---------------------------------------------------------------------------
// Kernel 3: fused reduce-over-64-chunks + squash + writeout.
// grid (B_, 4 k-quarters) = 128 blocks, block (16 k, 16 j) = 256 threads.
// Each thread: 64 independent strided loads (MLP-rich), smem cross-j reduce.
// ---------------------------------------------------------------------------
__global__ void squash_kernel(float* __restrict__ out) {
    __shared__ float vbuf[NU_][17];
    __shared__ float fbuf[16];
    const int b  = blockIdx.x;
    const int kq = blockIdx.y;
    const int kl = threadIdx.x;           // 0..15
    const int j  = threadIdx.y;           // 0..15
    const int k  = kq * 16 + kl;

    const float* __restrict__ p =
        g_part + ((size_t)b * NU_ + j) * US_ + k;
    float s = 0.f;
    #pragma unroll
    for (int c = 0; c < ICH; ++c)
        s += p[(size_t)c * (B_ * NU_ * US_)];

    vbuf[j][kl] = s;
    __syncthreads();

    if (j == 0) {
        float msq = 0.f;
        #pragma unroll
        for (int jj = 0; jj < NU_; ++jj) {
            float t = vbuf[jj][kl];
            msq += t * t;
        }
        fbuf[kl] = sqrtf(msq) / (1.0f + msq);
    }
    __syncthreads();

    out[((size_t)b * NU_ + j) * US_ + k] = s * fbuf[kl];
}

// ---------------------------------------------------------------------------
extern "C" void kernel_launch(void* const* d_in, const int* in_sizes, int n_in,
                              void* d_out, int out_size) {
    const float* x = (const float*)d_in[0];
    const float* W = (const float*)d_in[1];
    if (in_sizes[0] != B_ * IU_ * IC_) { const float* t = x; x = W; W = t; }

    prep_kernel<<<IC_ / 8, 256>>>(x);
    gemm_kernel<<<dim3(ICH, NU_ / 2), 256>>>(W);
    squash_kernel<<<dim3(B_, 4), dim3(16, 16)>>>((float*)d_out);
}